// round 5
// baseline (speedup 1.0000x reference)
#include <cuda_runtime.h>
#include <cstdint>

// ---------------- problem constants ----------------
#define N_ROWS  65536
#define D_LAT   64
#define KC      64
#define D_DATA  512
#define N_ITERS 10

#define TILE     128
#define NTILES   (N_ROWS / TILE)       // 512
#define GRID_IT  256
#define TPB      (NTILES / GRID_IT)    // 2

// smem float offsets
#define SF_C2   0
#define SF_RED  64
#define SF_ENC  320                    // [128][76]
#define SF_CT   (SF_ENC + 128*76)      // [64][72]  C^T: [d][k]
#define SF_R    (SF_CT + 64*72)        // [128][72] r:  [n][k]
#define SF_TOT  (SF_R + 128*72)        // 23872 floats = 95488 B

// ---------------- scratch globals ----------------
__device__ float g_C[KC * D_LAT];
__device__ float g_c2[KC];
__device__ float g_x2[N_ROWS];
__device__ float g_partC[GRID_IT * KC * D_LAT];
__device__ float g_partR[GRID_IT * KC];
__device__ float g_partLoss[GRID_IT];
__device__ float g_decPart[N_ITERS * GRID_IT];

// ---------------- mma.sync tf32 (m16n8k8) ----------------
__device__ __forceinline__ void mma_tf32(float* c, uint32_t a0, uint32_t a1,
                                         uint32_t a2, uint32_t a3,
                                         uint32_t b0, uint32_t b1) {
    asm volatile(
        "mma.sync.aligned.m16n8k8.row.col.f32.tf32.tf32.f32 "
        "{%0,%1,%2,%3}, {%4,%5,%6,%7}, {%8,%9}, {%0,%1,%2,%3};"
        : "+f"(c[0]), "+f"(c[1]), "+f"(c[2]), "+f"(c[3])
        : "r"(a0), "r"(a1), "r"(a2), "r"(a3), "r"(b0), "r"(b1));
}
__device__ __forceinline__ uint32_t fb(float x) { return __float_as_uint(x); }

// ---------------- small kernels ----------------
__global__ void x2_kernel(const float* __restrict__ enc) {
    int warp = threadIdx.x >> 5, lane = threadIdx.x & 31;
    int row = blockIdx.x * 8 + warp;
    const float2* e = reinterpret_cast<const float2*>(enc + (size_t)row * D_LAT);
    float2 v = e[lane];
    float s = v.x * v.x + v.y * v.y;
    #pragma unroll
    for (int off = 16; off; off >>= 1) s += __shfl_xor_sync(0xffffffffu, s, off);
    if (lane == 0) g_x2[row] = s;
}

__global__ void initC_kernel(const float* __restrict__ enc) {
    int k = blockIdx.x, d = threadIdx.x;
    float c = enc[k * D_LAT + d];
    g_C[k * D_LAT + d] = c;
    __shared__ float sh[64];
    sh[d] = c * c;
    __syncthreads();
    for (int off = 32; off; off >>= 1) { if (d < off) sh[d] += sh[d + off]; __syncthreads(); }
    if (d == 0) g_c2[k] = sh[0];
}

// 16 blocks x 256 threads: block covers 4 k-rows; thread -> one (k,d) output
__global__ void reduce_kernel() {
    int t = threadIdx.x;
    int k = blockIdx.x * 4 + (t >> 6), d = t & 63;
    float s = 0.f;
    #pragma unroll 8
    for (int b = 0; b < GRID_IT; b++) s += g_partC[(size_t)b * 4096 + k * 64 + d];
    __shared__ float srs[4];
    if (t < 128) {
        int j = t >> 5, ln = t & 31;
        float rs = 0.f;
        #pragma unroll
        for (int b = ln; b < GRID_IT; b += 32) rs += g_partR[b * 64 + blockIdx.x * 4 + j];
        #pragma unroll
        for (int off = 16; off; off >>= 1) rs += __shfl_xor_sync(0xffffffffu, rs, off);
        if (ln == 0) srs[j] = rs;
    }
    __syncthreads();
    float c = s / (srs[t >> 6] + 1e-8f);
    g_C[k * 64 + d] = c;
    __shared__ float sh[256];
    sh[t] = c * c;
    __syncthreads();
    for (int off = 32; off; off >>= 1) { if (d < off) sh[t] += sh[t + off]; __syncthreads(); }
    if (d == 0) g_c2[k] = sh[t];
}

__global__ void final_kernel(float* out) {
    __shared__ double sh[256];
    int t = threadIdx.x;
    double s = 0.0;
    for (int i = t; i < N_ITERS * GRID_IT; i += 256) s += (double)g_decPart[i];
    sh[t] = s;
    __syncthreads();
    for (int off = 128; off; off >>= 1) { if (t < off) sh[t] += sh[t + off]; __syncthreads(); }
    double decSum = sh[0];
    __syncthreads();
    s = 0.0;
    for (int i = t; i < GRID_IT; i += 256) s += (double)g_partLoss[i];
    sh[t] = s;
    __syncthreads();
    for (int off = 128; off; off >>= 1) { if (t < off) sh[t] += sh[t + off]; __syncthreads(); }
    if (t == 0) {
        double decLoss = decSum / ((double)N_ROWS * (double)D_DATA);
        double clLoss  = sh[0] / (double)N_ROWS;
        out[0] = (float)(decLoss + 0.001 * clLoss);
    }
}

// ---------------- main per-iteration kernel (mma.sync tf32 + dec slice) ----------------
__global__ void __launch_bounds__(256, 2)
iter_kernel(const float* __restrict__ enc,
            const float* __restrict__ X, const float* __restrict__ dec,
            int itIdx, int doLoss, int doUpdate) {
    extern __shared__ float sm[];
    float* sC2  = sm + SF_C2;
    float* sEnc = sm + SF_ENC;
    float* sCt  = sm + SF_CT;
    float* sR   = sm + SF_R;

    int t = threadIdx.x, w = t >> 5, lane = t & 31;
    int qr = lane >> 2, qc = lane & 3;   // quad row / quad col

    // ---- decoder-loss slice (1/10 of X/dec per iteration kernel) ----
    float decAcc = 0.f;
    {
        const int total4 = (N_ROWS * D_DATA) / 4;          // 8388608
        const int chunk = (total4 + N_ITERS - 1) / N_ITERS; // 838861
        int lo = itIdx * chunk;
        int hi = lo + chunk; if (hi > total4) hi = total4;
        const float4* x4 = reinterpret_cast<const float4*>(X);
        const float4* d4 = reinterpret_cast<const float4*>(dec);
        for (int i = lo + blockIdx.x * 256 + t; i < hi; i += GRID_IT * 256) {
            float4 a = x4[i], b = d4[i];
            float dx = a.x - b.x, dy = a.y - b.y, dz = a.z - b.z, dw = a.w - b.w;
            decAcc += dx * dx + dy * dy + dz * dz + dw * dw;
        }
    }

    // ---- one-time setup: C^T, c2, ones column ----
    for (int idx = t; idx < 4096; idx += 256) {
        int k = idx >> 6, d = idx & 63;
        sCt[d * 72 + k] = g_C[idx];
    }
    if (t < 64) sC2[t] = g_c2[t];
    if (t < 128) {
        sEnc[t * 76 + 64] = 1.0f;
        #pragma unroll
        for (int c = 65; c < 72; c++) sEnc[t * 76 + c] = 0.0f;
    }

    // gemm2 accumulators persist across tiles
    float acc2[5][4];
    #pragma unroll
    for (int i = 0; i < 5; i++)
        #pragma unroll
        for (int j = 0; j < 4; j++) acc2[i][j] = 0.f;

    int mb2  = (w & 3) * 16;          // gemm2 m-tile base (k-cluster rows)
    int ntlo = (w < 4) ? 0 : 4;
    int nN   = (w < 4) ? 4 : 5;

    float lossAcc = 0.f;

    for (int tt = 0; tt < TPB; tt++) {
        int n0 = (blockIdx.x * TPB + tt) * TILE;
        __syncthreads();   // prev gemm2 done reading sEnc/sR (and setup on tt=0)

        // ---- load enc tile [128][64] -> sEnc stride 76 ----
        const float4* eg = reinterpret_cast<const float4*>(enc + (size_t)n0 * D_LAT);
        #pragma unroll
        for (int i = 0; i < 8; i++) {
            int idx = i * 256 + t;
            int r = idx >> 4, c4 = idx & 15;
            *reinterpret_cast<float4*>(&sEnc[r * 76 + c4 * 4]) = eg[idx];
        }
        float x2a = g_x2[n0 + w * 16 + qr];
        float x2b = g_x2[n0 + w * 16 + qr + 8];
        __syncthreads();

        // ---- gemm1: D1[128 rows][64 k] = enc @ C^T ; warp w -> rows w*16..+15 ----
        float acc1[8][4];
        #pragma unroll
        for (int nt = 0; nt < 8; nt++)
            #pragma unroll
            for (int j = 0; j < 4; j++) acc1[nt][j] = 0.f;

        {
            const float* eRow = sEnc + (w * 16 + qr) * 76;
            #pragma unroll
            for (int ks = 0; ks < 8; ks++) {
                uint32_t a0 = fb(eRow[ks * 8 + qc]);
                uint32_t a1 = fb(eRow[8 * 76 + ks * 8 + qc]);
                uint32_t a2 = fb(eRow[ks * 8 + qc + 4]);
                uint32_t a3 = fb(eRow[8 * 76 + ks * 8 + qc + 4]);
                const float* ctk = sCt + (ks * 8 + qc) * 72;
                #pragma unroll
                for (int nt = 0; nt < 8; nt++) {
                    uint32_t b0 = fb(ctk[nt * 8 + qr]);
                    uint32_t b1 = fb(ctk[4 * 72 + nt * 8 + qr]);
                    mma_tf32(acc1[nt], a0, a1, a2, a3, b0, b1);
                }
            }
        }

        // ---- epilogue: d2, row softmax (rows r0=w*16+qr and r0+8) ----
        float mn0 = 3.4e38f, mn1 = 3.4e38f;
        #pragma unroll
        for (int nt = 0; nt < 8; nt++) {
            float c20 = sC2[nt * 8 + qc * 2];
            float c21 = sC2[nt * 8 + qc * 2 + 1];
            acc1[nt][0] = fmaxf(x2a + c20 - 2.f * acc1[nt][0], 0.f);
            acc1[nt][1] = fmaxf(x2a + c21 - 2.f * acc1[nt][1], 0.f);
            acc1[nt][2] = fmaxf(x2b + c20 - 2.f * acc1[nt][2], 0.f);
            acc1[nt][3] = fmaxf(x2b + c21 - 2.f * acc1[nt][3], 0.f);
            mn0 = fminf(mn0, fminf(acc1[nt][0], acc1[nt][1]));
            mn1 = fminf(mn1, fminf(acc1[nt][2], acc1[nt][3]));
        }
        mn0 = fminf(mn0, __shfl_xor_sync(0xffffffffu, mn0, 1));
        mn0 = fminf(mn0, __shfl_xor_sync(0xffffffffu, mn0, 2));
        mn1 = fminf(mn1, __shfl_xor_sync(0xffffffffu, mn1, 1));
        mn1 = fminf(mn1, __shfl_xor_sync(0xffffffffu, mn1, 2));

        float s0 = 0.f, s1 = 0.f, sl0 = 0.f, sl1 = 0.f;
        #pragma unroll
        for (int nt = 0; nt < 8; nt++) {
            float d2, e;
            d2 = acc1[nt][0]; e = __expf(mn0 - d2); s0 += e; sl0 += e * d2; acc1[nt][0] = e;
            d2 = acc1[nt][1]; e = __expf(mn0 - d2); s0 += e; sl0 += e * d2; acc1[nt][1] = e;
            d2 = acc1[nt][2]; e = __expf(mn1 - d2); s1 += e; sl1 += e * d2; acc1[nt][2] = e;
            d2 = acc1[nt][3]; e = __expf(mn1 - d2); s1 += e; sl1 += e * d2; acc1[nt][3] = e;
        }
        s0 += __shfl_xor_sync(0xffffffffu, s0, 1);  s0 += __shfl_xor_sync(0xffffffffu, s0, 2);
        s1 += __shfl_xor_sync(0xffffffffu, s1, 1);  s1 += __shfl_xor_sync(0xffffffffu, s1, 2);
        sl0 += __shfl_xor_sync(0xffffffffu, sl0, 1); sl0 += __shfl_xor_sync(0xffffffffu, sl0, 2);
        sl1 += __shfl_xor_sync(0xffffffffu, sl1, 1); sl1 += __shfl_xor_sync(0xffffffffu, sl1, 2);
        float inv0 = 1.f / s0, inv1 = 1.f / s1;
        if (doLoss) lossAcc += sl0 * inv0 * 0.25f + sl1 * inv1 * 0.25f;  // each quad-lane counts row/4

        if (doUpdate) {
            // ---- store r [n][k] stride 72 ----
            float* r0p = &sR[(w * 16 + qr) * 72];
            float* r1p = r0p + 8 * 72;
            #pragma unroll
            for (int nt = 0; nt < 8; nt++) {
                int col = nt * 8 + qc * 2;
                r0p[col]     = acc1[nt][0] * inv0;
                r0p[col + 1] = acc1[nt][1] * inv0;
                r1p[col]     = acc1[nt][2] * inv1;
                r1p[col + 1] = acc1[nt][3] * inv1;
            }
            __syncthreads();

            // ---- gemm2: D2[64 k][72] += r^T @ [enc | 1] ----
            #pragma unroll
            for (int ks = 0; ks < 16; ks++) {
                const float* rA = sR + (ks * 8 + qc) * 72 + mb2 + qr;
                const float* rB = sR + (ks * 8 + qc + 4) * 72 + mb2 + qr;
                uint32_t a0 = fb(rA[0]);
                uint32_t a1 = fb(rA[8]);
                uint32_t a2 = fb(rB[0]);
                uint32_t a3 = fb(rB[8]);
                const float* e0 = sEnc + (ks * 8 + qc) * 76 + qr;
                const float* e1 = sEnc + (ks * 8 + qc + 4) * 76 + qr;
                #pragma unroll
                for (int i = 0; i < 5; i++) {
                    if (i < nN) {
                        int nt = ntlo + i;
                        uint32_t b0 = fb(e0[nt * 8]);
                        uint32_t b1 = fb(e1[nt * 8]);
                        mma_tf32(acc2[i], a0, a1, a2, a3, b0, b1);
                    }
                }
            }
        }
    }

    // ---- write per-block partials ----
    if (doUpdate) {
        int k0 = mb2 + qr, k1 = k0 + 8;
        size_t base = (size_t)blockIdx.x * 4096;
        #pragma unroll
        for (int i = 0; i < 5; i++) {
            if (i < nN) {
                int nt = ntlo + i;
                if (nt < 8) {
                    int d = nt * 8 + qc * 2;
                    *reinterpret_cast<float2*>(&g_partC[base + k0 * 64 + d]) = make_float2(acc2[i][0], acc2[i][1]);
                    *reinterpret_cast<float2*>(&g_partC[base + k1 * 64 + d]) = make_float2(acc2[i][2], acc2[i][3]);
                } else if (qc == 0) {
                    g_partR[blockIdx.x * 64 + k0] = acc2[i][0];
                    g_partR[blockIdx.x * 64 + k1] = acc2[i][2];
                }
            }
        }
    }

    // ---- block reductions: dec slice, then loss ----
    float* red = sm + SF_RED;
    __syncthreads();
    red[t] = decAcc;
    __syncthreads();
    for (int off = 128; off; off >>= 1) { if (t < off) red[t] += red[t + off]; __syncthreads(); }
    if (t == 0) g_decPart[itIdx * GRID_IT + blockIdx.x] = red[0];

    if (doLoss) {
        __syncthreads();
        red[t] = lossAcc;
        __syncthreads();
        for (int off = 128; off; off >>= 1) { if (t < off) red[t] += red[t + off]; __syncthreads(); }
        if (t == 0) g_partLoss[blockIdx.x] = red[0];
    }
}

// ---------------- launch ----------------
extern "C" void kernel_launch(void* const* d_in, const int* in_sizes, int n_in,
                              void* d_out, int out_size) {
    const float* X   = (const float*)d_in[0];
    const float* enc = (const float*)d_in[1];
    const float* dec = (const float*)d_in[2];
    float* out = (float*)d_out;

    const int smemIter = SF_TOT * (int)sizeof(float);   // 95488 B
    cudaFuncSetAttribute(iter_kernel, cudaFuncAttributeMaxDynamicSharedMemorySize, smemIter);

    x2_kernel<<<N_ROWS / 8, 256>>>(enc);
    initC_kernel<<<KC, 64>>>(enc);
    for (int it = 0; it < N_ITERS; it++) {
        int last = (it == N_ITERS - 1);
        iter_kernel<<<GRID_IT, 256, smemIter>>>(enc, X, dec, it, last, !last);
        if (!last) reduce_kernel<<<16, 256>>>();
    }
    final_kernel<<<1, 256>>>(out);
}

// round 7
// speedup vs baseline: 1.2641x; 1.2641x over previous
#include <cuda_runtime.h>
#include <cstdint>

// ---------------- problem constants ----------------
#define N_ROWS  65536
#define D_LAT   64
#define KC      64
#define D_DATA  512
#define N_ITERS 10

#define TILE     128
#define NTILES   (N_ROWS / TILE)       // 512
#define GRID_IT  256
#define TPB      (NTILES / GRID_IT)    // 2

// smem float offsets
#define SF_C2   0
#define SF_RED  64
#define SF_ENC  320                    // [128][76]
#define SF_CT   (SF_ENC + 128*76)      // [64][72]  C^T: [d][k]
#define SF_R    (SF_CT + 64*72)        // [128][72] r:  [n][k]
#define SF_TOT  (SF_R + 128*72)        // 23872 floats = 95488 B

// ---------------- scratch globals ----------------
__device__ float g_C[KC * D_LAT];
__device__ float g_x2[N_ROWS];
__device__ float g_partC[GRID_IT * KC * D_LAT];
__device__ float g_partR[GRID_IT * KC];
__device__ float g_partLoss[GRID_IT];
__device__ float g_decPart[N_ITERS * GRID_IT];

// ---------------- mma.sync tf32 (m16n8k8) ----------------
__device__ __forceinline__ void mma_tf32(float* c, uint32_t a0, uint32_t a1,
                                         uint32_t a2, uint32_t a3,
                                         uint32_t b0, uint32_t b1) {
    asm volatile(
        "mma.sync.aligned.m16n8k8.row.col.f32.tf32.tf32.f32 "
        "{%0,%1,%2,%3}, {%4,%5,%6,%7}, {%8,%9}, {%0,%1,%2,%3};"
        : "+f"(c[0]), "+f"(c[1]), "+f"(c[2]), "+f"(c[3])
        : "r"(a0), "r"(a1), "r"(a2), "r"(a3), "r"(b0), "r"(b1));
}
__device__ __forceinline__ uint32_t fb(float x) { return __float_as_uint(x); }

// ---------------- small kernels ----------------
__global__ void x2_kernel(const float* __restrict__ enc) {
    int warp = threadIdx.x >> 5, lane = threadIdx.x & 31;
    int row = blockIdx.x * 8 + warp;
    const float2* e = reinterpret_cast<const float2*>(enc + (size_t)row * D_LAT);
    float2 v = e[lane];
    float s = v.x * v.x + v.y * v.y;
    #pragma unroll
    for (int off = 16; off; off >>= 1) s += __shfl_xor_sync(0xffffffffu, s, off);
    if (lane == 0) g_x2[row] = s;
}

__global__ void initC_kernel(const float* __restrict__ enc) {
    int idx = blockIdx.x * 256 + threadIdx.x;
    g_C[idx] = enc[idx];
}

// 256 blocks x 256 threads: block -> 16 (k,d) outputs; 16 b-lanes each sum 16 partials
__global__ void reduce_kernel() {
    __shared__ float red[256];
    __shared__ float sRs;
    int t = threadIdx.x;
    int base = blockIdx.x * 16;        // 16 consecutive d within k = blockIdx>>2
    int k = blockIdx.x >> 2;
    int out = t & 15, blane = t >> 4;
    float s = 0.f;
    #pragma unroll
    for (int i = 0; i < 16; i++)
        s += g_partC[(size_t)(blane + i * 16) * 4096 + base + out];
    red[blane * 16 + out] = s;
    if (t < 32) {
        float rs = 0.f;
        #pragma unroll
        for (int b = 0; b < 8; b++) rs += g_partR[(t + b * 32) * 64 + k];
        #pragma unroll
        for (int off = 16; off; off >>= 1) rs += __shfl_xor_sync(0xffffffffu, rs, off);
        if (t == 0) sRs = rs;
    }
    __syncthreads();
    #pragma unroll
    for (int off = 8; off; off >>= 1) {
        if (blane < off) red[blane * 16 + out] += red[(blane + off) * 16 + out];
        __syncthreads();
    }
    if (t < 16) g_C[base + t] = red[t] / (sRs + 1e-8f);
}

__global__ void final_kernel(float* out) {
    __shared__ double sh[256];
    int t = threadIdx.x;
    double s = 0.0;
    for (int i = t; i < N_ITERS * GRID_IT; i += 256) s += (double)g_decPart[i];
    sh[t] = s;
    __syncthreads();
    for (int off = 128; off; off >>= 1) { if (t < off) sh[t] += sh[t + off]; __syncthreads(); }
    double decSum = sh[0];
    __syncthreads();
    s = 0.0;
    for (int i = t; i < GRID_IT; i += 256) s += (double)g_partLoss[i];
    sh[t] = s;
    __syncthreads();
    for (int off = 128; off; off >>= 1) { if (t < off) sh[t] += sh[t + off]; __syncthreads(); }
    if (t == 0) {
        double decLoss = decSum / ((double)N_ROWS * (double)D_DATA);
        double clLoss  = sh[0] / (double)N_ROWS;
        out[0] = (float)(decLoss + 0.001 * clLoss);
    }
}

// ---------------- main per-iteration kernel (mma.sync tf32 + dec slice) ----------------
__global__ void __launch_bounds__(256, 2)
iter_kernel(const float* __restrict__ enc,
            const float* __restrict__ X, const float* __restrict__ dec,
            int itIdx, int doLoss, int doUpdate) {
    extern __shared__ float sm[];
    float* sC2  = sm + SF_C2;
    float* sRed = sm + SF_RED;
    float* sEnc = sm + SF_ENC;
    float* sCt  = sm + SF_CT;
    float* sR   = sm + SF_R;

    int t = threadIdx.x, w = t >> 5, lane = t & 31;
    int qr = lane >> 2, qc = lane & 3;   // quad row / quad col

    // ---- decoder-loss slice (1/10 of X/dec per iteration kernel) ----
    float decAcc = 0.f;
    {
        const int total4 = (N_ROWS * D_DATA) / 4;           // 8388608
        const int chunk = (total4 + N_ITERS - 1) / N_ITERS; // 838861
        int lo = itIdx * chunk;
        int hi = lo + chunk; if (hi > total4) hi = total4;
        const float4* x4 = reinterpret_cast<const float4*>(X);
        const float4* d4 = reinterpret_cast<const float4*>(dec);
        for (int i = lo + blockIdx.x * 256 + t; i < hi; i += GRID_IT * 256) {
            float4 a = x4[i], b = d4[i];
            float dx = a.x - b.x, dy = a.y - b.y, dz = a.z - b.z, dw = a.w - b.w;
            decAcc += dx * dx + dy * dy + dz * dz + dw * dw;
        }
    }

    // ---- one-time setup: C^T, ones column ----
    for (int idx = t; idx < 4096; idx += 256) {
        int k = idx >> 6, d = idx & 63;
        sCt[d * 72 + k] = g_C[idx];
    }
    if (t < 128) {
        sEnc[t * 76 + 64] = 1.0f;
        #pragma unroll
        for (int c = 65; c < 72; c++) sEnc[t * 76 + c] = 0.0f;
    }
    __syncthreads();

    // ---- c2[k] = sum_d C[k][d]^2, computed in-block from sCt ----
    {
        int k = t & 63, j = t >> 6;
        float s = 0.f;
        #pragma unroll
        for (int d = 0; d < 16; d++) {
            float v = sCt[(j * 16 + d) * 72 + k];
            s += v * v;
        }
        sRed[t] = s;
    }
    __syncthreads();
    if (t < 64) sC2[t] = sRed[t] + sRed[64 + t] + sRed[128 + t] + sRed[192 + t];

    // gemm2 accumulators persist across tiles
    float acc2[5][4];
    #pragma unroll
    for (int i = 0; i < 5; i++)
        #pragma unroll
        for (int j = 0; j < 4; j++) acc2[i][j] = 0.f;

    int mb2  = (w & 3) * 16;          // gemm2 m-tile base (k-cluster rows)
    int ntlo = (w < 4) ? 0 : 4;
    int nN   = (w < 4) ? 4 : 5;

    float lossAcc = 0.f;

    for (int tt = 0; tt < TPB; tt++) {
        int n0 = (blockIdx.x * TPB + tt) * TILE;
        __syncthreads();   // prev gemm2 done reading sEnc/sR (and c2 visibility on tt=0)

        // ---- load enc tile [128][64] -> sEnc stride 76 ----
        const float4* eg = reinterpret_cast<const float4*>(enc + (size_t)n0 * D_LAT);
        #pragma unroll
        for (int i = 0; i < 8; i++) {
            int idx = i * 256 + t;
            int r = idx >> 4, c4 = idx & 15;
            *reinterpret_cast<float4*>(&sEnc[r * 76 + c4 * 4]) = eg[idx];
        }
        float x2a = g_x2[n0 + w * 16 + qr];
        float x2b = g_x2[n0 + w * 16 + qr + 8];
        __syncthreads();

        // ---- gemm1: D1[128 rows][64 k] = enc @ C^T ; warp w -> rows w*16..+15 ----
        float acc1[8][4];
        #pragma unroll
        for (int nt = 0; nt < 8; nt++)
            #pragma unroll
            for (int j = 0; j < 4; j++) acc1[nt][j] = 0.f;

        {
            const float* eRow = sEnc + (w * 16 + qr) * 76;
            #pragma unroll
            for (int ks = 0; ks < 8; ks++) {
                uint32_t a0 = fb(eRow[ks * 8 + qc]);
                uint32_t a1 = fb(eRow[8 * 76 + ks * 8 + qc]);
                uint32_t a2 = fb(eRow[ks * 8 + qc + 4]);
                uint32_t a3 = fb(eRow[8 * 76 + ks * 8 + qc + 4]);
                const float* ctk = sCt + (ks * 8 + qc) * 72;
                #pragma unroll
                for (int nt = 0; nt < 8; nt++) {
                    uint32_t b0 = fb(ctk[nt * 8 + qr]);
                    uint32_t b1 = fb(ctk[4 * 72 + nt * 8 + qr]);
                    mma_tf32(acc1[nt], a0, a1, a2, a3, b0, b1);
                }
            }
        }

        // ---- epilogue: d2, row softmax (rows r0=w*16+qr and r0+8) ----
        float mn0 = 3.4e38f, mn1 = 3.4e38f;
        #pragma unroll
        for (int nt = 0; nt < 8; nt++) {
            float c20 = sC2[nt * 8 + qc * 2];
            float c21 = sC2[nt * 8 + qc * 2 + 1];
            acc1[nt][0] = fmaxf(x2a + c20 - 2.f * acc1[nt][0], 0.f);
            acc1[nt][1] = fmaxf(x2a + c21 - 2.f * acc1[nt][1], 0.f);
            acc1[nt][2] = fmaxf(x2b + c20 - 2.f * acc1[nt][2], 0.f);
            acc1[nt][3] = fmaxf(x2b + c21 - 2.f * acc1[nt][3], 0.f);
            mn0 = fminf(mn0, fminf(acc1[nt][0], acc1[nt][1]));
            mn1 = fminf(mn1, fminf(acc1[nt][2], acc1[nt][3]));
        }
        mn0 = fminf(mn0, __shfl_xor_sync(0xffffffffu, mn0, 1));
        mn0 = fminf(mn0, __shfl_xor_sync(0xffffffffu, mn0, 2));
        mn1 = fminf(mn1, __shfl_xor_sync(0xffffffffu, mn1, 1));
        mn1 = fminf(mn1, __shfl_xor_sync(0xffffffffu, mn1, 2));

        float s0 = 0.f, s1 = 0.f, sl0 = 0.f, sl1 = 0.f;
        #pragma unroll
        for (int nt = 0; nt < 8; nt++) {
            float d2, e;
            d2 = acc1[nt][0]; e = __expf(mn0 - d2); s0 += e; sl0 += e * d2; acc1[nt][0] = e;
            d2 = acc1[nt][1]; e = __expf(mn0 - d2); s0 += e; sl0 += e * d2; acc1[nt][1] = e;
            d2 = acc1[nt][2]; e = __expf(mn1 - d2); s1 += e; sl1 += e * d2; acc1[nt][2] = e;
            d2 = acc1[nt][3]; e = __expf(mn1 - d2); s1 += e; sl1 += e * d2; acc1[nt][3] = e;
        }
        s0 += __shfl_xor_sync(0xffffffffu, s0, 1);  s0 += __shfl_xor_sync(0xffffffffu, s0, 2);
        s1 += __shfl_xor_sync(0xffffffffu, s1, 1);  s1 += __shfl_xor_sync(0xffffffffu, s1, 2);
        sl0 += __shfl_xor_sync(0xffffffffu, sl0, 1); sl0 += __shfl_xor_sync(0xffffffffu, sl0, 2);
        sl1 += __shfl_xor_sync(0xffffffffu, sl1, 1); sl1 += __shfl_xor_sync(0xffffffffu, sl1, 2);
        float inv0 = 1.f / s0, inv1 = 1.f / s1;
        if (doLoss) lossAcc += sl0 * inv0 * 0.25f + sl1 * inv1 * 0.25f;  // each quad-lane counts row/4

        if (doUpdate) {
            // ---- store r [n][k] stride 72 ----
            float* r0p = &sR[(w * 16 + qr) * 72];
            float* r1p = r0p + 8 * 72;
            #pragma unroll
            for (int nt = 0; nt < 8; nt++) {
                int col = nt * 8 + qc * 2;
                r0p[col]     = acc1[nt][0] * inv0;
                r0p[col + 1] = acc1[nt][1] * inv0;
                r1p[col]     = acc1[nt][2] * inv1;
                r1p[col + 1] = acc1[nt][3] * inv1;
            }
            __syncthreads();

            // ---- gemm2: D2[64 k][72] += r^T @ [enc | 1] ----
            #pragma unroll
            for (int ks = 0; ks < 16; ks++) {
                const float* rA = sR + (ks * 8 + qc) * 72 + mb2 + qr;
                const float* rB = sR + (ks * 8 + qc + 4) * 72 + mb2 + qr;
                uint32_t a0 = fb(rA[0]);
                uint32_t a1 = fb(rA[8]);
                uint32_t a2 = fb(rB[0]);
                uint32_t a3 = fb(rB[8]);
                const float* e0 = sEnc + (ks * 8 + qc) * 76 + qr;
                const float* e1 = sEnc + (ks * 8 + qc + 4) * 76 + qr;
                #pragma unroll
                for (int i = 0; i < 5; i++) {
                    if (i < nN) {
                        int nt = ntlo + i;
                        uint32_t b0 = fb(e0[nt * 8]);
                        uint32_t b1 = fb(e1[nt * 8]);
                        mma_tf32(acc2[i], a0, a1, a2, a3, b0, b1);
                    }
                }
            }
        }
    }

    // ---- write per-block partials ----
    if (doUpdate) {
        int k0 = mb2 + qr, k1 = k0 + 8;
        size_t base = (size_t)blockIdx.x * 4096;
        #pragma unroll
        for (int i = 0; i < 5; i++) {
            if (i < nN) {
                int nt = ntlo + i;
                if (nt < 8) {
                    int d = nt * 8 + qc * 2;
                    *reinterpret_cast<float2*>(&g_partC[base + k0 * 64 + d]) = make_float2(acc2[i][0], acc2[i][1]);
                    *reinterpret_cast<float2*>(&g_partC[base + k1 * 64 + d]) = make_float2(acc2[i][2], acc2[i][3]);
                } else if (qc == 0) {
                    g_partR[blockIdx.x * 64 + k0] = acc2[i][0];
                    g_partR[blockIdx.x * 64 + k1] = acc2[i][2];
                }
            }
        }
    }

    // ---- block reductions: dec slice, then loss ----
    __syncthreads();
    sRed[t] = decAcc;
    __syncthreads();
    for (int off = 128; off; off >>= 1) { if (t < off) sRed[t] += sRed[t + off]; __syncthreads(); }
    if (t == 0) g_decPart[itIdx * GRID_IT + blockIdx.x] = sRed[0];

    if (doLoss) {
        __syncthreads();
        sRed[t] = lossAcc;
        __syncthreads();
        for (int off = 128; off; off >>= 1) { if (t < off) sRed[t] += sRed[t + off]; __syncthreads(); }
        if (t == 0) g_partLoss[blockIdx.x] = sRed[0];
    }
}

// ---------------- launch ----------------
extern "C" void kernel_launch(void* const* d_in, const int* in_sizes, int n_in,
                              void* d_out, int out_size) {
    const float* X   = (const float*)d_in[0];
    const float* enc = (const float*)d_in[1];
    const float* dec = (const float*)d_in[2];
    float* out = (float*)d_out;

    const int smemIter = SF_TOT * (int)sizeof(float);   // 95488 B
    cudaFuncSetAttribute(iter_kernel, cudaFuncAttributeMaxDynamicSharedMemorySize, smemIter);

    x2_kernel<<<N_ROWS / 8, 256>>>(enc);
    initC_kernel<<<16, 256>>>(enc);
    for (int it = 0; it < N_ITERS; it++) {
        int last = (it == N_ITERS - 1);
        iter_kernel<<<GRID_IT, 256, smemIter>>>(enc, X, dec, it, last, !last);
        if (!last) reduce_kernel<<<256, 256>>>();
    }
    final_kernel<<<1, 256>>>(out);
}

// round 10
// speedup vs baseline: 1.2738x; 1.0077x over previous
#include <cuda_runtime.h>
#include <cstdint>

// ---------------- problem constants ----------------
#define N_ROWS  65536
#define D_LAT   64
#define KC      64
#define D_DATA  512
#define N_ITERS 10

#define TILE     128
#define NTILES   (N_ROWS / TILE)       // 512
#define GRID_IT  256
#define TPB      (NTILES / GRID_IT)    // 2

// smem float offsets
#define SF_C2   0
#define SF_RED  64
#define SF_ENC  320                    // [128][76]
#define SF_CT   (SF_ENC + 128*76)      // [64][72]  C^T: [d][k]
#define SF_R    (SF_CT + 64*72)        // [128][72] r:  [n][k]
#define SF_TOT  (SF_R + 128*72)        // 23872 floats = 95488 B

// ---------------- scratch globals ----------------
__device__ float g_C[KC * D_LAT];
__device__ float g_x2[N_ROWS];
__device__ float g_partC[GRID_IT * KC * D_LAT];
__device__ float g_partR[GRID_IT * KC];
__device__ float g_partLoss[GRID_IT];
__device__ float g_decPart[N_ITERS * GRID_IT];

// ---------------- mma.sync tf32 (m16n8k8) ----------------
__device__ __forceinline__ void mma_tf32(float* c, uint32_t a0, uint32_t a1,
                                         uint32_t a2, uint32_t a3,
                                         uint32_t b0, uint32_t b1) {
    asm volatile(
        "mma.sync.aligned.m16n8k8.row.col.f32.tf32.tf32.f32 "
        "{%0,%1,%2,%3}, {%4,%5,%6,%7}, {%8,%9}, {%0,%1,%2,%3};"
        : "+f"(c[0]), "+f"(c[1]), "+f"(c[2]), "+f"(c[3])
        : "r"(a0), "r"(a1), "r"(a2), "r"(a3), "r"(b0), "r"(b1));
}
__device__ __forceinline__ uint32_t fb(float x) { return __float_as_uint(x); }

// ---------------- small kernels ----------------
__global__ void x2_kernel(const float* __restrict__ enc) {
    int warp = threadIdx.x >> 5, lane = threadIdx.x & 31;
    int row = blockIdx.x * 8 + warp;
    const float2* e = reinterpret_cast<const float2*>(enc + (size_t)row * D_LAT);
    float2 v = e[lane];
    float s = v.x * v.x + v.y * v.y;
    #pragma unroll
    for (int off = 16; off; off >>= 1) s += __shfl_xor_sync(0xffffffffu, s, off);
    if (lane == 0) g_x2[row] = s;
}

__global__ void initC_kernel(const float* __restrict__ enc) {
    int idx = blockIdx.x * 256 + threadIdx.x;
    g_C[idx] = enc[idx];
}

// 128 blocks x 256 threads, fully vectorized (LDG.128):
// block -> k = bid>>1, d-range = (bid&1)*32 .. +32 (8 float4 outputs)
// thread: f4 = t&7 (which float4), blane = t>>3 (0..31) sums 8 partials
__global__ void reduce_kernel() {
    __shared__ float4 red4[32 * 8];
    __shared__ float sRs;
    int t = threadIdx.x;
    int k = blockIdx.x >> 1;
    int dbase = (blockIdx.x & 1) * 32;
    int f4 = t & 7, blane = t >> 3;

    float4 s = make_float4(0.f, 0.f, 0.f, 0.f);
    #pragma unroll
    for (int i = 0; i < 8; i++) {
        int b = blane + i * 32;
        float4 v = *reinterpret_cast<const float4*>(&g_partC[(size_t)b * 4096 + k * 64 + dbase + f4 * 4]);
        s.x += v.x; s.y += v.y; s.z += v.z; s.w += v.w;
    }
    red4[blane * 8 + f4] = s;

    if (t < 32) {
        float rs = 0.f;
        #pragma unroll
        for (int j = 0; j < 8; j++) rs += g_partR[(t + j * 32) * 64 + k];
        #pragma unroll
        for (int off = 16; off; off >>= 1) rs += __shfl_xor_sync(0xffffffffu, rs, off);
        if (t == 0) sRs = rs;
    }
    __syncthreads();
    #pragma unroll
    for (int off = 16; off; off >>= 1) {
        if (blane < off) {
            float4 a = red4[blane * 8 + f4], b = red4[(blane + off) * 8 + f4];
            a.x += b.x; a.y += b.y; a.z += b.z; a.w += b.w;
            red4[blane * 8 + f4] = a;
        }
        __syncthreads();
    }
    if (t < 8) {
        float inv = 1.f / (sRs + 1e-8f);
        float4 a = red4[t];
        *reinterpret_cast<float4*>(&g_C[k * 64 + dbase + t * 4]) =
            make_float4(a.x * inv, a.y * inv, a.z * inv, a.w * inv);
    }
}

__global__ void final_kernel(float* out) {
    __shared__ double sh[256];
    int t = threadIdx.x;
    double s = 0.0;
    for (int i = t; i < N_ITERS * GRID_IT; i += 256) s += (double)g_decPart[i];
    sh[t] = s;
    __syncthreads();
    for (int off = 128; off; off >>= 1) { if (t < off) sh[t] += sh[t + off]; __syncthreads(); }
    double decSum = sh[0];
    __syncthreads();
    s = 0.0;
    for (int i = t; i < GRID_IT; i += 256) s += (double)g_partLoss[i];
    sh[t] = s;
    __syncthreads();
    for (int off = 128; off; off >>= 1) { if (t < off) sh[t] += sh[t + off]; __syncthreads(); }
    if (t == 0) {
        double decLoss = decSum / ((double)N_ROWS * (double)D_DATA);
        double clLoss  = sh[0] / (double)N_ROWS;
        out[0] = (float)(decLoss + 0.001 * clLoss);
    }
}

// ---------------- main per-iteration kernel (mma.sync tf32 + dec slice) ----------------
__global__ void __launch_bounds__(256, 2)
iter_kernel(const float* __restrict__ enc,
            const float* __restrict__ X, const float* __restrict__ dec,
            int itIdx, int doLoss, int doUpdate) {
    extern __shared__ float sm[];
    float* sC2  = sm + SF_C2;
    float* sRed = sm + SF_RED;
    float* sEnc = sm + SF_ENC;
    float* sCt  = sm + SF_CT;
    float* sR   = sm + SF_R;

    int t = threadIdx.x, w = t >> 5, lane = t & 31;
    int qr = lane >> 2, qc = lane & 3;   // quad row / quad col

    // ---- decoder-loss slice (1/10 of X/dec per iteration kernel) ----
    float decAcc = 0.f;
    {
        const int total4 = (N_ROWS * D_DATA) / 4;           // 8388608
        const int chunk = (total4 + N_ITERS - 1) / N_ITERS; // 838861
        int lo = itIdx * chunk;
        int hi = lo + chunk; if (hi > total4) hi = total4;
        const float4* x4 = reinterpret_cast<const float4*>(X);
        const float4* d4 = reinterpret_cast<const float4*>(dec);
        for (int i = lo + blockIdx.x * 256 + t; i < hi; i += GRID_IT * 256) {
            float4 a = x4[i], b = d4[i];
            float dx = a.x - b.x, dy = a.y - b.y, dz = a.z - b.z, dw = a.w - b.w;
            decAcc += dx * dx + dy * dy + dz * dz + dw * dw;
        }
    }

    // ---- one-time setup: C^T, ones column ----
    for (int idx = t; idx < 4096; idx += 256) {
        int k = idx >> 6, d = idx & 63;
        sCt[d * 72 + k] = g_C[idx];
    }
    if (t < 128) {
        sEnc[t * 76 + 64] = 1.0f;
        #pragma unroll
        for (int c = 65; c < 72; c++) sEnc[t * 76 + c] = 0.0f;
    }
    __syncthreads();

    // ---- c2[k] = sum_d C[k][d]^2, computed in-block from sCt ----
    {
        int k = t & 63, j = t >> 6;
        float s = 0.f;
        #pragma unroll
        for (int d = 0; d < 16; d++) {
            float v = sCt[(j * 16 + d) * 72 + k];
            s += v * v;
        }
        sRed[t] = s;
    }
    __syncthreads();
    if (t < 64) sC2[t] = sRed[t] + sRed[64 + t] + sRed[128 + t] + sRed[192 + t];

    // gemm2 accumulators persist across tiles
    float acc2[5][4];
    #pragma unroll
    for (int i = 0; i < 5; i++)
        #pragma unroll
        for (int j = 0; j < 4; j++) acc2[i][j] = 0.f;

    int mb2  = (w & 3) * 16;          // gemm2 m-tile base (k-cluster rows)
    int ntlo = (w < 4) ? 0 : 4;
    int nN   = (w < 4) ? 4 : 5;

    float lossAcc = 0.f;

    for (int tt = 0; tt < TPB; tt++) {
        int n0 = (blockIdx.x * TPB + tt) * TILE;
        __syncthreads();   // prev gemm2 done reading sEnc/sR (and c2 visibility on tt=0)

        // ---- load enc tile [128][64] -> sEnc stride 76 ----
        const float4* eg = reinterpret_cast<const float4*>(enc + (size_t)n0 * D_LAT);
        #pragma unroll
        for (int i = 0; i < 8; i++) {
            int idx = i * 256 + t;
            int r = idx >> 4, c4 = idx & 15;
            *reinterpret_cast<float4*>(&sEnc[r * 76 + c4 * 4]) = eg[idx];
        }
        float x2a = g_x2[n0 + w * 16 + qr];
        float x2b = g_x2[n0 + w * 16 + qr + 8];
        __syncthreads();

        // ---- gemm1: D1[128 rows][64 k] = enc @ C^T ; warp w -> rows w*16..+15 ----
        float acc1[8][4];
        #pragma unroll
        for (int nt = 0; nt < 8; nt++)
            #pragma unroll
            for (int j = 0; j < 4; j++) acc1[nt][j] = 0.f;

        {
            const float* eRow = sEnc + (w * 16 + qr) * 76;
            #pragma unroll
            for (int ks = 0; ks < 8; ks++) {
                uint32_t a0 = fb(eRow[ks * 8 + qc]);
                uint32_t a1 = fb(eRow[8 * 76 + ks * 8 + qc]);
                uint32_t a2 = fb(eRow[ks * 8 + qc + 4]);
                uint32_t a3 = fb(eRow[8 * 76 + ks * 8 + qc + 4]);
                const float* ctk = sCt + (ks * 8 + qc) * 72;
                #pragma unroll
                for (int nt = 0; nt < 8; nt++) {
                    uint32_t b0 = fb(ctk[nt * 8 + qr]);
                    uint32_t b1 = fb(ctk[4 * 72 + nt * 8 + qr]);
                    mma_tf32(acc1[nt], a0, a1, a2, a3, b0, b1);
                }
            }
        }

        // ---- epilogue: d2, row softmax (rows r0=w*16+qr and r0+8) ----
        float mn0 = 3.4e38f, mn1 = 3.4e38f;
        #pragma unroll
        for (int nt = 0; nt < 8; nt++) {
            float c20 = sC2[nt * 8 + qc * 2];
            float c21 = sC2[nt * 8 + qc * 2 + 1];
            acc1[nt][0] = fmaxf(x2a + c20 - 2.f * acc1[nt][0], 0.f);
            acc1[nt][1] = fmaxf(x2a + c21 - 2.f * acc1[nt][1], 0.f);
            acc1[nt][2] = fmaxf(x2b + c20 - 2.f * acc1[nt][2], 0.f);
            acc1[nt][3] = fmaxf(x2b + c21 - 2.f * acc1[nt][3], 0.f);
            mn0 = fminf(mn0, fminf(acc1[nt][0], acc1[nt][1]));
            mn1 = fminf(mn1, fminf(acc1[nt][2], acc1[nt][3]));
        }
        mn0 = fminf(mn0, __shfl_xor_sync(0xffffffffu, mn0, 1));
        mn0 = fminf(mn0, __shfl_xor_sync(0xffffffffu, mn0, 2));
        mn1 = fminf(mn1, __shfl_xor_sync(0xffffffffu, mn1, 1));
        mn1 = fminf(mn1, __shfl_xor_sync(0xffffffffu, mn1, 2));

        float s0 = 0.f, s1 = 0.f, sl0 = 0.f, sl1 = 0.f;
        #pragma unroll
        for (int nt = 0; nt < 8; nt++) {
            float d2, e;
            d2 = acc1[nt][0]; e = __expf(mn0 - d2); s0 += e; sl0 += e * d2; acc1[nt][0] = e;
            d2 = acc1[nt][1]; e = __expf(mn0 - d2); s0 += e; sl0 += e * d2; acc1[nt][1] = e;
            d2 = acc1[nt][2]; e = __expf(mn1 - d2); s1 += e; sl1 += e * d2; acc1[nt][2] = e;
            d2 = acc1[nt][3]; e = __expf(mn1 - d2); s1 += e; sl1 += e * d2; acc1[nt][3] = e;
        }
        s0 += __shfl_xor_sync(0xffffffffu, s0, 1);  s0 += __shfl_xor_sync(0xffffffffu, s0, 2);
        s1 += __shfl_xor_sync(0xffffffffu, s1, 1);  s1 += __shfl_xor_sync(0xffffffffu, s1, 2);
        sl0 += __shfl_xor_sync(0xffffffffu, sl0, 1); sl0 += __shfl_xor_sync(0xffffffffu, sl0, 2);
        sl1 += __shfl_xor_sync(0xffffffffu, sl1, 1); sl1 += __shfl_xor_sync(0xffffffffu, sl1, 2);
        float inv0 = 1.f / s0, inv1 = 1.f / s1;
        if (doLoss) lossAcc += sl0 * inv0 * 0.25f + sl1 * inv1 * 0.25f;  // each quad-lane counts row/4

        if (doUpdate) {
            // ---- store r [n][k] stride 72 ----
            float* r0p = &sR[(w * 16 + qr) * 72];
            float* r1p = r0p + 8 * 72;
            #pragma unroll
            for (int nt = 0; nt < 8; nt++) {
                int col = nt * 8 + qc * 2;
                r0p[col]     = acc1[nt][0] * inv0;
                r0p[col + 1] = acc1[nt][1] * inv0;
                r1p[col]     = acc1[nt][2] * inv1;
                r1p[col + 1] = acc1[nt][3] * inv1;
            }
            __syncthreads();

            // ---- gemm2: D2[64 k][72] += r^T @ [enc | 1] ----
            #pragma unroll
            for (int ks = 0; ks < 16; ks++) {
                const float* rA = sR + (ks * 8 + qc) * 72 + mb2 + qr;
                const float* rB = sR + (ks * 8 + qc + 4) * 72 + mb2 + qr;
                uint32_t a0 = fb(rA[0]);
                uint32_t a1 = fb(rA[8]);
                uint32_t a2 = fb(rB[0]);
                uint32_t a3 = fb(rB[8]);
                const float* e0 = sEnc + (ks * 8 + qc) * 76 + qr;
                const float* e1 = sEnc + (ks * 8 + qc + 4) * 76 + qr;
                #pragma unroll
                for (int i = 0; i < 5; i++) {
                    if (i < nN) {
                        int nt = ntlo + i;
                        uint32_t b0 = fb(e0[nt * 8]);
                        uint32_t b1 = fb(e1[nt * 8]);
                        mma_tf32(acc2[i], a0, a1, a2, a3, b0, b1);
                    }
                }
            }
        }
    }

    // ---- write per-block partials ----
    if (doUpdate) {
        int k0 = mb2 + qr, k1 = k0 + 8;
        size_t base = (size_t)blockIdx.x * 4096;
        #pragma unroll
        for (int i = 0; i < 5; i++) {
            if (i < nN) {
                int nt = ntlo + i;
                if (nt < 8) {
                    int d = nt * 8 + qc * 2;
                    *reinterpret_cast<float2*>(&g_partC[base + k0 * 64 + d]) = make_float2(acc2[i][0], acc2[i][1]);
                    *reinterpret_cast<float2*>(&g_partC[base + k1 * 64 + d]) = make_float2(acc2[i][2], acc2[i][3]);
                } else if (qc == 0) {
                    g_partR[blockIdx.x * 64 + k0] = acc2[i][0];
                    g_partR[blockIdx.x * 64 + k1] = acc2[i][2];
                }
            }
        }
    }

    // ---- block reductions: dec slice, then loss ----
    __syncthreads();
    sRed[t] = decAcc;
    __syncthreads();
    for (int off = 128; off; off >>= 1) { if (t < off) sRed[t] += sRed[t + off]; __syncthreads(); }
    if (t == 0) g_decPart[itIdx * GRID_IT + blockIdx.x] = sRed[0];

    if (doLoss) {
        __syncthreads();
        sRed[t] = lossAcc;
        __syncthreads();
        for (int off = 128; off; off >>= 1) { if (t < off) sRed[t] += sRed[t + off]; __syncthreads(); }
        if (t == 0) g_partLoss[blockIdx.x] = sRed[0];
    }
}

// ---------------- launch ----------------
extern "C" void kernel_launch(void* const* d_in, const int* in_sizes, int n_in,
                              void* d_out, int out_size) {
    const float* X   = (const float*)d_in[0];
    const float* enc = (const float*)d_in[1];
    const float* dec = (const float*)d_in[2];
    float* out = (float*)d_out;

    const int smemIter = SF_TOT * (int)sizeof(float);   // 95488 B
    cudaFuncSetAttribute(iter_kernel, cudaFuncAttributeMaxDynamicSharedMemorySize, smemIter);

    x2_kernel<<<N_ROWS / 8, 256>>>(enc);
    initC_kernel<<<16, 256>>>(enc);
    for (int it = 0; it < N_ITERS; it++) {
        int last = (it == N_ITERS - 1);
        iter_kernel<<<GRID_IT, 256, smemIter>>>(enc, X, dec, it, last, !last);
        if (!last) reduce_kernel<<<128, 256>>>();
    }
    final_kernel<<<1, 256>>>(out);
}

// round 11
// speedup vs baseline: 1.3461x; 1.0567x over previous
#include <cuda_runtime.h>
#include <cstdint>

// ---------------- problem constants ----------------
#define N_ROWS  65536
#define D_LAT   64
#define KC      64
#define D_DATA  512
#define N_ITERS 10

#define TILE     128
#define GRID_IT  256
#define TPB      2                     // tiles per block (256*2*128 = 65536 rows)

// smem float offsets
#define SF_C2   0                      // [64]
#define SF_RED  64                     // [256]
#define SF_X2   320                    // [256]  x2 for this block's rows
#define SF_ENC  576                    // [128][76]
#define SF_CT   (SF_ENC + 128*76)      // [64][72]  C^T: [d][k]
#define SF_R    (SF_CT + 64*72)        // [128][72] r:  [n][k]
#define SF_TOT  (SF_R + 128*72)        // 24128 floats = 96512 B

// ---------------- scratch globals ----------------
__device__ float g_C[KC * D_LAT];
__device__ float g_partC[GRID_IT * KC * D_LAT];
__device__ float g_partR[GRID_IT * KC];
__device__ float g_partLoss[GRID_IT];
__device__ float g_decPart[GRID_IT];

// grid barrier state (returns to initial state after every full barrier)
__device__ unsigned g_barArr = 0;
__device__ volatile unsigned g_barGen = 0;

__device__ __forceinline__ void gridBar() {
    __syncthreads();
    if (threadIdx.x == 0) {
        __threadfence();                       // publish this block's global writes
        unsigned gen = g_barGen;
        if (atomicAdd(&g_barArr, 1u) == GRID_IT - 1) {
            g_barArr = 0;
            __threadfence();
            g_barGen = gen + 1;
        } else {
            while (g_barGen == gen) { __nanosleep(64); }
            __threadfence();                   // acquire others' writes
        }
    }
    __syncthreads();
}

// ---------------- mma.sync tf32 (m16n8k8) ----------------
__device__ __forceinline__ void mma_tf32(float* c, uint32_t a0, uint32_t a1,
                                         uint32_t a2, uint32_t a3,
                                         uint32_t b0, uint32_t b1) {
    asm volatile(
        "mma.sync.aligned.m16n8k8.row.col.f32.tf32.tf32.f32 "
        "{%0,%1,%2,%3}, {%4,%5,%6,%7}, {%8,%9}, {%0,%1,%2,%3};"
        : "+f"(c[0]), "+f"(c[1]), "+f"(c[2]), "+f"(c[3])
        : "r"(a0), "r"(a1), "r"(a2), "r"(a3), "r"(b0), "r"(b1));
}
__device__ __forceinline__ uint32_t fb(float x) { return __float_as_uint(x); }

// ---------------- the whole problem in one persistent kernel ----------------
__global__ void __launch_bounds__(256, 2)
fused_kernel(const float* __restrict__ enc,
             const float* __restrict__ X, const float* __restrict__ dec,
             float* __restrict__ out) {
    extern __shared__ float sm[];
    float* sC2  = sm + SF_C2;
    float* sRed = sm + SF_RED;
    float* sX2  = sm + SF_X2;
    float* sEnc = sm + SF_ENC;
    float* sCt  = sm + SF_CT;
    float* sR   = sm + SF_R;

    int t = threadIdx.x, w = t >> 5, lane = t & 31;
    int bid = blockIdx.x;
    int qr = lane >> 2, qc = lane & 3;   // quad row / quad col

    // ---- prologue: x2 for this block's 256 rows; ones column for gemm2 ----
    {
        int rowBase = bid * 256 + w * 32;
        for (int i = 0; i < 32; i++) {
            const float2* e = reinterpret_cast<const float2*>(enc + (size_t)(rowBase + i) * D_LAT);
            float2 v = e[lane];
            float s = v.x * v.x + v.y * v.y;
            #pragma unroll
            for (int off = 16; off; off >>= 1) s += __shfl_xor_sync(0xffffffffu, s, off);
            if (lane == 0) sX2[w * 32 + i] = s;
        }
    }
    if (t < 128) {
        sEnc[t * 76 + 64] = 1.0f;
        #pragma unroll
        for (int c = 65; c < 72; c++) sEnc[t * 76 + c] = 0.0f;
    }

    int mb2  = (w & 3) * 16;          // gemm2 m-tile base (k-cluster rows)
    int ntlo = (w < 4) ? 0 : 4;
    int nN   = (w < 4) ? 4 : 5;

    float decAcc = 0.f;
    float lossAcc = 0.f;

    const int total4 = (N_ROWS * D_DATA) / 4;            // 8388608
    const int chunk = (total4 + N_ITERS - 1) / N_ITERS;  // 838861
    const float4* x4 = reinterpret_cast<const float4*>(X);
    const float4* d4 = reinterpret_cast<const float4*>(dec);

    for (int it = 0; it < N_ITERS; it++) {
        int doUpdate = (it < N_ITERS - 1);
        int doLoss   = (it == N_ITERS - 1);

        // ---- load C^T (iter 0: directly from enc[:64]) ----
        const float* csrc = (it == 0) ? enc : g_C;
        __syncthreads();                      // sCt safe to overwrite (all passed barrier/tiles)
        for (int idx = t; idx < 4096; idx += 256) {
            int k = idx >> 6, d = idx & 63;
            sCt[d * 72 + k] = csrc[idx];
        }
        __syncthreads();

        // ---- c2[k] = sum_d C[k][d]^2 ----
        {
            int k = t & 63, j = t >> 6;
            float s = 0.f;
            #pragma unroll
            for (int d = 0; d < 16; d++) {
                float v = sCt[(j * 16 + d) * 72 + k];
                s += v * v;
            }
            sRed[t] = s;
        }
        __syncthreads();
        if (t < 64) sC2[t] = sRed[t] + sRed[64 + t] + sRed[128 + t] + sRed[192 + t];

        // gemm2 accumulators (per iteration)
        float acc2[5][4];
        #pragma unroll
        for (int i = 0; i < 5; i++)
            #pragma unroll
            for (int j = 0; j < 4; j++) acc2[i][j] = 0.f;

        for (int tt = 0; tt < TPB; tt++) {
            int n0 = (bid * TPB + tt) * TILE;
            __syncthreads();   // prev gemm2 done reading sEnc/sR; sC2 visible on tt=0

            // ---- load enc tile [128][64] -> sEnc stride 76 ----
            const float4* eg = reinterpret_cast<const float4*>(enc + (size_t)n0 * D_LAT);
            #pragma unroll
            for (int i = 0; i < 8; i++) {
                int idx = i * 256 + t;
                int r = idx >> 4, c4 = idx & 15;
                *reinterpret_cast<float4*>(&sEnc[r * 76 + c4 * 4]) = eg[idx];
            }
            float x2a = sX2[tt * 128 + w * 16 + qr];
            float x2b = sX2[tt * 128 + w * 16 + qr + 8];
            __syncthreads();

            // ---- gemm1: D1[128][64] = enc @ C^T ; warp w -> rows w*16..+15 ----
            float acc1[8][4];
            #pragma unroll
            for (int nt = 0; nt < 8; nt++)
                #pragma unroll
                for (int j = 0; j < 4; j++) acc1[nt][j] = 0.f;

            {
                const float* eRow = sEnc + (w * 16 + qr) * 76;
                #pragma unroll
                for (int ks = 0; ks < 8; ks++) {
                    uint32_t a0 = fb(eRow[ks * 8 + qc]);
                    uint32_t a1 = fb(eRow[8 * 76 + ks * 8 + qc]);
                    uint32_t a2 = fb(eRow[ks * 8 + qc + 4]);
                    uint32_t a3 = fb(eRow[8 * 76 + ks * 8 + qc + 4]);
                    const float* ctk = sCt + (ks * 8 + qc) * 72;
                    #pragma unroll
                    for (int nt = 0; nt < 8; nt++) {
                        uint32_t b0 = fb(ctk[nt * 8 + qr]);
                        uint32_t b1 = fb(ctk[4 * 72 + nt * 8 + qr]);
                        mma_tf32(acc1[nt], a0, a1, a2, a3, b0, b1);
                    }
                }
            }

            // ---- epilogue: d2, row softmax ----
            float mn0 = 3.4e38f, mn1 = 3.4e38f;
            #pragma unroll
            for (int nt = 0; nt < 8; nt++) {
                float c20 = sC2[nt * 8 + qc * 2];
                float c21 = sC2[nt * 8 + qc * 2 + 1];
                acc1[nt][0] = fmaxf(x2a + c20 - 2.f * acc1[nt][0], 0.f);
                acc1[nt][1] = fmaxf(x2a + c21 - 2.f * acc1[nt][1], 0.f);
                acc1[nt][2] = fmaxf(x2b + c20 - 2.f * acc1[nt][2], 0.f);
                acc1[nt][3] = fmaxf(x2b + c21 - 2.f * acc1[nt][3], 0.f);
                mn0 = fminf(mn0, fminf(acc1[nt][0], acc1[nt][1]));
                mn1 = fminf(mn1, fminf(acc1[nt][2], acc1[nt][3]));
            }
            mn0 = fminf(mn0, __shfl_xor_sync(0xffffffffu, mn0, 1));
            mn0 = fminf(mn0, __shfl_xor_sync(0xffffffffu, mn0, 2));
            mn1 = fminf(mn1, __shfl_xor_sync(0xffffffffu, mn1, 1));
            mn1 = fminf(mn1, __shfl_xor_sync(0xffffffffu, mn1, 2));

            float s0 = 0.f, s1 = 0.f, sl0 = 0.f, sl1 = 0.f;
            #pragma unroll
            for (int nt = 0; nt < 8; nt++) {
                float d2, e;
                d2 = acc1[nt][0]; e = __expf(mn0 - d2); s0 += e; sl0 += e * d2; acc1[nt][0] = e;
                d2 = acc1[nt][1]; e = __expf(mn0 - d2); s0 += e; sl0 += e * d2; acc1[nt][1] = e;
                d2 = acc1[nt][2]; e = __expf(mn1 - d2); s1 += e; sl1 += e * d2; acc1[nt][2] = e;
                d2 = acc1[nt][3]; e = __expf(mn1 - d2); s1 += e; sl1 += e * d2; acc1[nt][3] = e;
            }
            s0 += __shfl_xor_sync(0xffffffffu, s0, 1);  s0 += __shfl_xor_sync(0xffffffffu, s0, 2);
            s1 += __shfl_xor_sync(0xffffffffu, s1, 1);  s1 += __shfl_xor_sync(0xffffffffu, s1, 2);
            sl0 += __shfl_xor_sync(0xffffffffu, sl0, 1); sl0 += __shfl_xor_sync(0xffffffffu, sl0, 2);
            sl1 += __shfl_xor_sync(0xffffffffu, sl1, 1); sl1 += __shfl_xor_sync(0xffffffffu, sl1, 2);
            float inv0 = 1.f / s0, inv1 = 1.f / s1;
            if (doLoss) lossAcc += sl0 * inv0 * 0.25f + sl1 * inv1 * 0.25f;

            if (doUpdate) {
                // ---- store r [n][k] stride 72 ----
                float* r0p = &sR[(w * 16 + qr) * 72];
                float* r1p = r0p + 8 * 72;
                #pragma unroll
                for (int nt = 0; nt < 8; nt++) {
                    int col = nt * 8 + qc * 2;
                    r0p[col]     = acc1[nt][0] * inv0;
                    r0p[col + 1] = acc1[nt][1] * inv0;
                    r1p[col]     = acc1[nt][2] * inv1;
                    r1p[col + 1] = acc1[nt][3] * inv1;
                }
                __syncthreads();

                // ---- gemm2: D2[64 k][72] += r^T @ [enc | 1] ----
                #pragma unroll
                for (int ks = 0; ks < 16; ks++) {
                    const float* rA = sR + (ks * 8 + qc) * 72 + mb2 + qr;
                    const float* rB = sR + (ks * 8 + qc + 4) * 72 + mb2 + qr;
                    uint32_t a0 = fb(rA[0]);
                    uint32_t a1 = fb(rA[8]);
                    uint32_t a2 = fb(rB[0]);
                    uint32_t a3 = fb(rB[8]);
                    const float* e0 = sEnc + (ks * 8 + qc) * 76 + qr;
                    const float* e1 = sEnc + (ks * 8 + qc + 4) * 76 + qr;
                    #pragma unroll
                    for (int i = 0; i < 5; i++) {
                        if (i < nN) {
                            int nt = ntlo + i;
                            uint32_t b0 = fb(e0[nt * 8]);
                            uint32_t b1 = fb(e1[nt * 8]);
                            mma_tf32(acc2[i], a0, a1, a2, a3, b0, b1);
                        }
                    }
                }
            }
        }

        if (doUpdate) {
            // ---- write per-block partials ----
            {
                int k0 = mb2 + qr, k1 = k0 + 8;
                size_t base = (size_t)bid * 4096;
                #pragma unroll
                for (int i = 0; i < 5; i++) {
                    if (i < nN) {
                        int nt = ntlo + i;
                        if (nt < 8) {
                            int d = nt * 8 + qc * 2;
                            *reinterpret_cast<float2*>(&g_partC[base + k0 * 64 + d]) = make_float2(acc2[i][0], acc2[i][1]);
                            *reinterpret_cast<float2*>(&g_partC[base + k1 * 64 + d]) = make_float2(acc2[i][2], acc2[i][3]);
                        } else if (qc == 0) {
                            g_partR[bid * 64 + k0] = acc2[i][0];
                            g_partR[bid * 64 + k1] = acc2[i][2];
                        }
                    }
                }
            }
            gridBar();   // all partials visible

            // ---- reduce my 16 C-outputs (outputs base bid*16, k = bid>>2) ----
            {
                int base = bid * 16, k = bid >> 2;
                int outc = t & 15, blane = t >> 4;
                float s = 0.f;
                #pragma unroll
                for (int i = 0; i < 16; i++)
                    s += g_partC[(size_t)(blane + i * 16) * 4096 + base + outc];
                sRed[blane * 16 + outc] = s;
                __shared__ float sRs;
                if (t < 32) {
                    float rs = 0.f;
                    #pragma unroll
                    for (int j = 0; j < 8; j++) rs += g_partR[(t + j * 32) * 64 + k];
                    #pragma unroll
                    for (int off = 16; off; off >>= 1) rs += __shfl_xor_sync(0xffffffffu, rs, off);
                    if (t == 0) sRs = rs;
                }
                __syncthreads();
                #pragma unroll
                for (int off = 8; off; off >>= 1) {
                    if (blane < off) sRed[blane * 16 + outc] += sRed[(blane + off) * 16 + outc];
                    __syncthreads();
                }
                if (t < 16) g_C[base + t] = sRed[t] / (sRs + 1e-8f);
            }

            // ---- decoder-loss slice for this iteration (overlaps barrier skew) ----
            {
                int lo = it * chunk;
                int hi = lo + chunk; if (hi > total4) hi = total4;
                for (int i = lo + bid * 256 + t; i < hi; i += GRID_IT * 256) {
                    float4 a = x4[i], b = d4[i];
                    float dx = a.x - b.x, dy = a.y - b.y, dz = a.z - b.z, dw = a.w - b.w;
                    decAcc += dx * dx + dy * dy + dz * dz + dw * dw;
                }
            }
            gridBar();   // g_C fully updated before next iteration loads it
        } else {
            // last iteration: just the final dec slice
            int lo = it * chunk;
            int hi = lo + chunk; if (hi > total4) hi = total4;
            for (int i = lo + bid * 256 + t; i < hi; i += GRID_IT * 256) {
                float4 a = x4[i], b = d4[i];
                float dx = a.x - b.x, dy = a.y - b.y, dz = a.z - b.z, dw = a.w - b.w;
                decAcc += dx * dx + dy * dy + dz * dz + dw * dw;
            }
        }
    }

    // ---- per-block reductions of dec + loss ----
    __syncthreads();
    sRed[t] = decAcc;
    __syncthreads();
    for (int off = 128; off; off >>= 1) { if (t < off) sRed[t] += sRed[t + off]; __syncthreads(); }
    if (t == 0) g_decPart[bid] = sRed[0];

    __syncthreads();
    sRed[t] = lossAcc;
    __syncthreads();
    for (int off = 128; off; off >>= 1) { if (t < off) sRed[t] += sRed[t + off]; __syncthreads(); }
    if (t == 0) g_partLoss[bid] = sRed[0];

    gridBar();

    // ---- block 0: final combine ----
    if (bid == 0) {
        __shared__ double sh[256];
        double s = (double)g_decPart[t];
        sh[t] = s;
        __syncthreads();
        for (int off = 128; off; off >>= 1) { if (t < off) sh[t] += sh[t + off]; __syncthreads(); }
        double decSum = sh[0];
        __syncthreads();
        sh[t] = (double)g_partLoss[t];
        __syncthreads();
        for (int off = 128; off; off >>= 1) { if (t < off) sh[t] += sh[t + off]; __syncthreads(); }
        if (t == 0) {
            double decLoss = decSum / ((double)N_ROWS * (double)D_DATA);
            double clLoss  = sh[0] / (double)N_ROWS;
            out[0] = (float)(decLoss + 0.001 * clLoss);
        }
    }
}

// ---------------- launch ----------------
extern "C" void kernel_launch(void* const* d_in, const int* in_sizes, int n_in,
                              void* d_out, int out_size) {
    const float* X   = (const float*)d_in[0];
    const float* enc = (const float*)d_in[1];
    const float* dec = (const float*)d_in[2];
    float* out = (float*)d_out;

    const int smemB = SF_TOT * (int)sizeof(float);   // 96512 B
    cudaFuncSetAttribute(fused_kernel, cudaFuncAttributeMaxDynamicSharedMemorySize, smemB);

    fused_kernel<<<GRID_IT, 256, smemB>>>(enc, X, dec, out);
}

// round 12
// speedup vs baseline: 1.3589x; 1.0095x over previous
#include <cuda_runtime.h>
#include <cstdint>

// ---------------- problem constants ----------------
#define N_ROWS  65536
#define D_LAT   64
#define KC      64
#define D_DATA  512
#define N_ITERS 10

#define TILE     128
#define GRID_IT  256
#define TPB      2                     // tiles per block
#define BLK      384                   // 12 warps: 8 compute + 4 dec-streamer

// smem float offsets
#define SF_C2   0                      // [64]
#define SF_RED  64                     // [384] (+[256] slot for rs)
#define SF_X2   448                    // [256]
#define SF_ENC  704                    // [128][76]
#define SF_CT   (SF_ENC + 128*76)      // [64][72]
#define SF_R    (SF_CT + 64*72)        // [128][72]
#define SF_TOT  (SF_R + 128*72)        // 24256 floats = 97024 B

// ---------------- scratch globals ----------------
__device__ float g_C[KC * D_LAT];
__device__ float g_partC[GRID_IT * KC * D_LAT];
__device__ float g_partR[GRID_IT * KC];
__device__ float g_partLoss[GRID_IT];
__device__ float g_decPart[GRID_IT];

// grid barrier (returns to initial state after each full barrier)
__device__ unsigned g_barArr = 0;
__device__ volatile unsigned g_barGen = 0;

__device__ __forceinline__ void gridBar() {
    __syncthreads();
    if (threadIdx.x == 0) {
        __threadfence();
        unsigned gen = g_barGen;
        if (atomicAdd(&g_barArr, 1u) == GRID_IT - 1) {
            g_barArr = 0;
            __threadfence();
            g_barGen = gen + 1;
        } else {
            while (g_barGen == gen) { __nanosleep(64); }
            __threadfence();
        }
    }
    __syncthreads();
}

// ---------------- mma.sync tf32 (m16n8k8) ----------------
__device__ __forceinline__ void mma_tf32(float* c, uint32_t a0, uint32_t a1,
                                         uint32_t a2, uint32_t a3,
                                         uint32_t b0, uint32_t b1) {
    asm volatile(
        "mma.sync.aligned.m16n8k8.row.col.f32.tf32.tf32.f32 "
        "{%0,%1,%2,%3}, {%4,%5,%6,%7}, {%8,%9}, {%0,%1,%2,%3};"
        : "+f"(c[0]), "+f"(c[1]), "+f"(c[2]), "+f"(c[3])
        : "r"(a0), "r"(a1), "r"(a2), "r"(a3), "r"(b0), "r"(b1));
}
__device__ __forceinline__ uint32_t fb(float x) { return __float_as_uint(x); }

// ---------------- one persistent kernel ----------------
__global__ void __launch_bounds__(BLK, 2)
fused_kernel(const float* __restrict__ enc,
             const float* __restrict__ X, const float* __restrict__ dec,
             float* __restrict__ out) {
    extern __shared__ float sm[];
    float* sC2  = sm + SF_C2;
    float* sRed = sm + SF_RED;
    float* sX2  = sm + SF_X2;
    float* sEnc = sm + SF_ENC;
    float* sCt  = sm + SF_CT;
    float* sR   = sm + SF_R;

    int t = threadIdx.x, w = t >> 5, lane = t & 31;
    int bid = blockIdx.x;
    int qr = lane >> 2, qc = lane & 3;
    bool isCompute = (w < 8);
    int dt = t - 256;                  // dec-warp lane index (0..127) when w>=8

    // ---- prologue: x2 for this block's 256 rows (compute warps); ones cols ----
    if (isCompute) {
        int rowBase = bid * 256 + w * 32;
        for (int i = 0; i < 32; i++) {
            const float2* e = reinterpret_cast<const float2*>(enc + (size_t)(rowBase + i) * D_LAT);
            float2 v = e[lane];
            float s = v.x * v.x + v.y * v.y;
            #pragma unroll
            for (int off = 16; off; off >>= 1) s += __shfl_xor_sync(0xffffffffu, s, off);
            if (lane == 0) sX2[w * 32 + i] = s;
        }
    }
    if (t < 128) {
        sEnc[t * 76 + 64] = 1.0f;
        #pragma unroll
        for (int c = 65; c < 72; c++) sEnc[t * 76 + c] = 0.0f;
    }

    int m2  = (w & 3) * 16;            // gemm2 m-tile base (k-cluster rows)
    int nb2 = w >> 2;                  // gemm2 n-tile family: {nb2, nb2+3, nb2+6}

    float decAcc = 0.f, lossAcc = 0.f;
    const int total4 = (N_ROWS * D_DATA) / 4;            // 8388608
    const int chunk = (total4 + N_ITERS - 1) / N_ITERS;  // 838861
    const float4* x4 = reinterpret_cast<const float4*>(X);
    const float4* d4 = reinterpret_cast<const float4*>(dec);

    for (int it = 0; it < N_ITERS; it++) {
        int doUpdate = (it < N_ITERS - 1);
        int doLoss   = (it == N_ITERS - 1);

        // ---- load C^T (iter 0: straight from enc[:64]) ----
        const float* csrc = (it == 0) ? enc : g_C;
        __syncthreads();
        for (int idx = t; idx < 4096; idx += BLK) {
            int k = idx >> 6, d = idx & 63;
            sCt[d * 72 + k] = csrc[idx];
        }
        __syncthreads();

        // ---- c2[k] = sum_d C[k][d]^2 ----
        if (t < 256) {
            int k = t & 63, j = t >> 6;
            float s = 0.f;
            #pragma unroll
            for (int d = 0; d < 16; d++) {
                float v = sCt[(j * 16 + d) * 72 + k];
                s += v * v;
            }
            sRed[t] = s;
        }
        __syncthreads();
        if (t < 64) sC2[t] = sRed[t] + sRed[64 + t] + sRed[128 + t] + sRed[192 + t];

        float acc2[3][4];
        #pragma unroll
        for (int i = 0; i < 3; i++)
            #pragma unroll
            for (int j = 0; j < 4; j++) acc2[i][j] = 0.f;

        for (int tt = 0; tt < TPB; tt++) {
            int n0 = (bid * TPB + tt) * TILE;
            __syncthreads();   // sEnc/sR reuse safe; sC2 visible on tt=0

            // ---- load enc tile (all 12 warps) ----
            const float4* eg = reinterpret_cast<const float4*>(enc + (size_t)n0 * D_LAT);
            for (int idx = t; idx < 2048; idx += BLK) {
                int r = idx >> 4, c4 = idx & 15;
                *reinterpret_cast<float4*>(&sEnc[r * 76 + c4 * 4]) = eg[idx];
            }
            __syncthreads();

            if (isCompute) {
                float x2a = sX2[tt * 128 + w * 16 + qr];
                float x2b = sX2[tt * 128 + w * 16 + qr + 8];

                // ---- gemm1: dot[128][64] = enc @ C^T ----
                float acc1[8][4];
                #pragma unroll
                for (int nt = 0; nt < 8; nt++)
                    #pragma unroll
                    for (int j = 0; j < 4; j++) acc1[nt][j] = 0.f;
                {
                    const float* eRow = sEnc + (w * 16 + qr) * 76;
                    #pragma unroll
                    for (int ks = 0; ks < 8; ks++) {
                        uint32_t a0 = fb(eRow[ks * 8 + qc]);
                        uint32_t a1 = fb(eRow[8 * 76 + ks * 8 + qc]);
                        uint32_t a2 = fb(eRow[ks * 8 + qc + 4]);
                        uint32_t a3 = fb(eRow[8 * 76 + ks * 8 + qc + 4]);
                        const float* ctk = sCt + (ks * 8 + qc) * 72;
                        #pragma unroll
                        for (int nt = 0; nt < 8; nt++) {
                            uint32_t b0 = fb(ctk[nt * 8 + qr]);
                            uint32_t b1 = fb(ctk[4 * 72 + nt * 8 + qr]);
                            mma_tf32(acc1[nt], a0, a1, a2, a3, b0, b1);
                        }
                    }
                }

                // ---- epilogue on v = 2*dot - c2 (x2 cancels in softmax) ----
                float mx0 = -3.4e38f, mx1 = -3.4e38f;
                #pragma unroll
                for (int nt = 0; nt < 8; nt++) {
                    float c20 = sC2[nt * 8 + qc * 2];
                    float c21 = sC2[nt * 8 + qc * 2 + 1];
                    float v;
                    v = fmaf(2.f, acc1[nt][0], -c20); acc1[nt][0] = v; mx0 = fmaxf(mx0, v);
                    v = fmaf(2.f, acc1[nt][1], -c21); acc1[nt][1] = v; mx0 = fmaxf(mx0, v);
                    v = fmaf(2.f, acc1[nt][2], -c20); acc1[nt][2] = v; mx1 = fmaxf(mx1, v);
                    v = fmaf(2.f, acc1[nt][3], -c21); acc1[nt][3] = v; mx1 = fmaxf(mx1, v);
                }
                mx0 = fmaxf(mx0, __shfl_xor_sync(0xffffffffu, mx0, 1));
                mx0 = fmaxf(mx0, __shfl_xor_sync(0xffffffffu, mx0, 2));
                mx1 = fmaxf(mx1, __shfl_xor_sync(0xffffffffu, mx1, 1));
                mx1 = fmaxf(mx1, __shfl_xor_sync(0xffffffffu, mx1, 2));

                float s0 = 0.f, s1 = 0.f, sl0 = 0.f, sl1 = 0.f;
                #pragma unroll
                for (int nt = 0; nt < 8; nt++) {
                    float v, e;
                    v = acc1[nt][0]; e = __expf(v - mx0); s0 += e; acc1[nt][0] = e;
                    if (doLoss) sl0 += e * fmaxf(x2a - v, 0.f);
                    v = acc1[nt][1]; e = __expf(v - mx0); s0 += e; acc1[nt][1] = e;
                    if (doLoss) sl0 += e * fmaxf(x2a - v, 0.f);
                    v = acc1[nt][2]; e = __expf(v - mx1); s1 += e; acc1[nt][2] = e;
                    if (doLoss) sl1 += e * fmaxf(x2b - v, 0.f);
                    v = acc1[nt][3]; e = __expf(v - mx1); s1 += e; acc1[nt][3] = e;
                    if (doLoss) sl1 += e * fmaxf(x2b - v, 0.f);
                }
                s0 += __shfl_xor_sync(0xffffffffu, s0, 1);  s0 += __shfl_xor_sync(0xffffffffu, s0, 2);
                s1 += __shfl_xor_sync(0xffffffffu, s1, 1);  s1 += __shfl_xor_sync(0xffffffffu, s1, 2);
                float inv0 = 1.f / s0, inv1 = 1.f / s1;
                if (doLoss) {
                    sl0 += __shfl_xor_sync(0xffffffffu, sl0, 1); sl0 += __shfl_xor_sync(0xffffffffu, sl0, 2);
                    sl1 += __shfl_xor_sync(0xffffffffu, sl1, 1); sl1 += __shfl_xor_sync(0xffffffffu, sl1, 2);
                    lossAcc += (sl0 * inv0 + sl1 * inv1) * 0.25f;
                }

                if (doUpdate) {
                    float* r0p = &sR[(w * 16 + qr) * 72];
                    float* r1p = r0p + 8 * 72;
                    #pragma unroll
                    for (int nt = 0; nt < 8; nt++) {
                        int col = nt * 8 + qc * 2;
                        *reinterpret_cast<float2*>(&r0p[col]) = make_float2(acc1[nt][0] * inv0, acc1[nt][1] * inv0);
                        *reinterpret_cast<float2*>(&r1p[col]) = make_float2(acc1[nt][2] * inv1, acc1[nt][3] * inv1);
                    }
                }
            } else {
                // ---- dec-loss streamers: this (it, tt)'s slice ----
                int lo = it * chunk;
                int hi = lo + chunk; if (hi > total4) hi = total4;
                for (int i = lo + bid * 256 + tt * 128 + dt; i < hi; i += GRID_IT * 256) {
                    float4 a = x4[i], b = d4[i];
                    float dx = a.x - b.x, dy = a.y - b.y, dz = a.z - b.z, dw = a.w - b.w;
                    decAcc += dx * dx + dy * dy + dz * dz + dw * dw;
                }
            }
            __syncthreads();

            if (doUpdate) {
                // ---- gemm2 (all 12 warps): D2[64][72] += r^T @ [enc | 1] ----
                #pragma unroll
                for (int ks = 0; ks < 16; ks++) {
                    const float* rA = sR + (ks * 8 + qc) * 72 + m2 + qr;
                    const float* rB = sR + (ks * 8 + qc + 4) * 72 + m2 + qr;
                    uint32_t a0 = fb(rA[0]);
                    uint32_t a1 = fb(rA[8]);
                    uint32_t a2 = fb(rB[0]);
                    uint32_t a3 = fb(rB[8]);
                    const float* e0 = sEnc + (ks * 8 + qc) * 76 + qr;
                    const float* e1 = sEnc + (ks * 8 + qc + 4) * 76 + qr;
                    #pragma unroll
                    for (int j = 0; j < 3; j++) {
                        int nt = nb2 + 3 * j;
                        uint32_t b0 = fb(e0[nt * 8]);
                        uint32_t b1 = fb(e1[nt * 8]);
                        mma_tf32(acc2[j], a0, a1, a2, a3, b0, b1);
                    }
                }
            }
        }

        if (doUpdate) {
            // ---- write per-block partials ----
            {
                int k0 = m2 + qr, k1 = k0 + 8;
                size_t base = (size_t)bid * 4096;
                #pragma unroll
                for (int j = 0; j < 3; j++) {
                    int nt = nb2 + 3 * j;
                    if (nt < 8) {
                        int d = nt * 8 + qc * 2;
                        *reinterpret_cast<float2*>(&g_partC[base + k0 * 64 + d]) = make_float2(acc2[j][0], acc2[j][1]);
                        *reinterpret_cast<float2*>(&g_partC[base + k1 * 64 + d]) = make_float2(acc2[j][2], acc2[j][3]);
                    } else if (qc == 0) {
                        g_partR[bid * 64 + k0] = acc2[j][0];
                        g_partR[bid * 64 + k1] = acc2[j][2];
                    }
                }
            }
            gridBar();   // all partials visible

            // ---- reduce my 16 C-outputs ----
            {
                int baseo = bid * 16, kk = bid >> 2;
                if (t < 256) {
                    int outc = t & 15, blane = t >> 4;
                    float s = 0.f;
                    #pragma unroll
                    for (int i = 0; i < 16; i++)
                        s += g_partC[(size_t)(blane + i * 16) * 4096 + baseo + outc];
                    sRed[t] = s;
                }
                if (t < 32) {
                    float rs = 0.f;
                    #pragma unroll
                    for (int j = 0; j < 8; j++) rs += g_partR[(t + j * 32) * 64 + kk];
                    #pragma unroll
                    for (int off = 16; off; off >>= 1) rs += __shfl_xor_sync(0xffffffffu, rs, off);
                    if (t == 0) sRed[256] = rs;
                }
                __syncthreads();
                #pragma unroll
                for (int off = 128; off >= 16; off >>= 1) {
                    if (t < off) sRed[t] += sRed[t + off];
                    __syncthreads();
                }
                if (t < 16) g_C[baseo + t] = sRed[t] / (sRed[256] + 1e-8f);
            }
            gridBar();   // g_C complete before next iteration
        }
    }

    // ---- per-block reductions: dec, then loss (384 threads) ----
    __syncthreads();
    sRed[t] = decAcc;
    __syncthreads();
    if (t < 128) sRed[t] += sRed[t + 256];
    __syncthreads();
    for (int off = 128; off; off >>= 1) { if (t < off) sRed[t] += sRed[t + off]; __syncthreads(); }
    if (t == 0) g_decPart[bid] = sRed[0];

    __syncthreads();
    sRed[t] = lossAcc;
    __syncthreads();
    if (t < 128) sRed[t] += sRed[t + 256];
    __syncthreads();
    for (int off = 128; off; off >>= 1) { if (t < off) sRed[t] += sRed[t + off]; __syncthreads(); }
    if (t == 0) g_partLoss[bid] = sRed[0];

    gridBar();

    // ---- block 0: final combine ----
    if (bid == 0) {
        __shared__ double sh[256];
        if (t < 256) sh[t] = (double)g_decPart[t];
        __syncthreads();
        for (int off = 128; off; off >>= 1) { if (t < off) sh[t] += sh[t + off]; __syncthreads(); }
        double decSum = sh[0];
        __syncthreads();
        if (t < 256) sh[t] = (double)g_partLoss[t];
        __syncthreads();
        for (int off = 128; off; off >>= 1) { if (t < off) sh[t] += sh[t + off]; __syncthreads(); }
        if (t == 0) {
            double decLoss = decSum / ((double)N_ROWS * (double)D_DATA);
            double clLoss  = sh[0] / (double)N_ROWS;
            out[0] = (float)(decLoss + 0.001 * clLoss);
        }
    }
}

// ---------------- launch ----------------
extern "C" void kernel_launch(void* const* d_in, const int* in_sizes, int n_in,
                              void* d_out, int out_size) {
    const float* X   = (const float*)d_in[0];
    const float* enc = (const float*)d_in[1];
    const float* dec = (const float*)d_in[2];
    float* out = (float*)d_out;

    const int smemB = SF_TOT * (int)sizeof(float);   // 97024 B
    cudaFuncSetAttribute(fused_kernel, cudaFuncAttributeMaxDynamicSharedMemorySize, smemB);

    fused_kernel<<<GRID_IT, BLK, smemB>>>(enc, X, dec, out);
}